// round 4
// baseline (speedup 1.0000x reference)
#include <cuda_runtime.h>

// AlarmworkRNN collapsed to a vector RNN (only sequence row 2047 matters).
// Round 4: barrier eliminated. State is published as tagged 16B chunks
// (payload + step tag in one 128-bit store); consumers spin on the data
// itself. 2 syncthreads/step, out-GEMV overlapped with z-GEMVs.

#define GRID  128
#define BLOCK 576        // 16 z-warps + 2 C/out-warps
#define KEXT  1280       // 256 (x) + 1024 (state)
#define NSTEP 256

__device__ unsigned g_epoch;                 // bumped each launch
__device__ float4   g_pub[2][GRID * 6];      // [parity][cta*6 + slot] tagged chunks

__global__ void rnn_init_kernel() { g_epoch += 1u; }

__device__ __forceinline__ float4 ld_vol4(const float4* p) {
    float4 u;
    asm volatile("ld.volatile.global.v4.f32 {%0,%1,%2,%3}, [%4];"
                 : "=f"(u.x), "=f"(u.y), "=f"(u.z), "=f"(u.w)
                 : "l"(p) : "memory");
    return u;
}
__device__ __forceinline__ void st_vol4(float4* p, float4 u) {
    asm volatile("st.volatile.global.v4.f32 [%0], {%1,%2,%3,%4};"
                 :: "l"(p), "f"(u.x), "f"(u.y), "f"(u.z), "f"(u.w) : "memory");
}

__global__ __launch_bounds__(BLOCK, 1)
void rnn_persistent_kernel(const float* __restrict__ x,
                           const float* __restrict__ W_in1,
                           const float* __restrict__ b_in1,
                           const float* __restrict__ W_rec1,
                           const float* __restrict__ W_in2,
                           const float* __restrict__ b_in2,
                           const float* __restrict__ W_rec2,
                           const float* __restrict__ W_out,
                           const float* __restrict__ b_out,
                           float* __restrict__ out)
{
    extern __shared__ float sm[];
    float* wso     = sm;                 // [2][1024] out weights
    float* A1      = wso + 2048;         // [KEXT] [x | z1]
    float* A2      = A1 + KEXT;          // [KEXT] [0 | z2]   (x-region stays 0)
    float* B2      = A2 + KEXT;          // [KEXT] [x | z2]   (B2 == A2 + KEXT)
    float* redp    = B2 + KEXT;          // [2][8][8] partials
    float* pubv    = redp + 128;         // [16] publish staging
    float* sbias   = pubv + 16;          // [16]
    float* scratch = sbias + 16;         // [4] dead-drop for invalid scatter slots
    float* stage   = scratch + 4;        // [8*KEXT] weight staging (preload only)

    const int tid  = threadIdx.x;
    const int warp = tid >> 5;
    const int lane = tid & 31;
    const int j0   = blockIdx.x * 8;
    const int o0   = blockIdx.x * 2;

    const bool isZ = (warp < 16);
    const int role = warp >> 3;          // 0/1 for z-warps, 2 for C-warps
    const int w8   = warp & 7;
    const int o_l  = lane >> 2;
    const int g_l  = lane & 3;
    const int cw   = warp - 16;          // 0,1 for C-warps

    const unsigned epoch = g_epoch;

    // ---- Preload ----
    for (int idx = tid; idx < 2048; idx += BLOCK) {
        int j = idx >> 1, c = idx & 1;
        wso[c * 1024 + j] = W_out[j * 256 + o0 + c];
    }
    if (tid < 8)       sbias[tid] = b_in1[j0 + tid];
    else if (tid < 16) sbias[tid] = b_in2[j0 + tid - 8];

    // zero A2 entirely (x-region stays 0 forever) and state regions of A1/B2
    for (int idx = tid; idx < KEXT; idx += BLOCK) {
        A2[idx] = 0.0f;
        if (idx >= 256) { A1[idx] = 0.0f; B2[idx] = 0.0f; }
    }

    float wreg[40];
    for (int round = 0; round < 2; round++) {
        for (int idx = tid; idx < 8 * KEXT; idx += BLOCK) {
            int k = idx >> 3, o = idx & 7, j = j0 + o;
            float v;
            if (round == 0)
                v = (k < 256) ? W_in1[k * 1024 + j] : W_rec1[(k - 256) * 1024 + j];
            else
                v = (k < 256) ? W_in2[k * 1024 + j] : W_rec2[(k - 256) * 1024 + j];
            stage[o * KEXT + k] = v;
        }
        __syncthreads();
        if (isZ && role == round) {
            const float* src = stage + o_l * KEXT + w8 * 160 + g_l * 40;
            #pragma unroll
            for (int i = 0; i < 40; i++) wreg[i] = src[i];
        }
        __syncthreads();
    }

    // C-warps: x(0) into A1/B2, prefetch x(1); out bias
    float4 xreg4 = make_float4(0.f, 0.f, 0.f, 0.f);
    float bo = 0.0f;
    if (!isZ) {
        int ct = tid - 512;  // 0..63
        float4 v = ((const float4*)(x + (size_t)2047 * 256))[ct];
        ((float4*)A1)[ct] = v;
        ((float4*)B2)[ct] = v;
        xreg4 = ((const float4*)(x + ((size_t)1 * 2048 + 2047) * 256))[ct];
        bo = b_out[o0 + cw];
    }

    // Precompute scatter targets for this thread's poll chunks.
    // chunk m: c=m/6, slot=m%6, r=slot/3, q=slot%3; payload s -> j=3q+s (j<8)
    float* d0[3]; float* d1[3];
    bool dual0 = false, dual1 = false;
    {
        int ms[2] = { tid, 512 + tid };
        for (int h = 0; h < 2; h++) {
            float** d = (h == 0) ? d0 : d1;
            int m = ms[h];
            if ((h == 0 && tid < 512) || (h == 1 && tid < 256)) {
                int c = m / 6, slot = m % 6, r = slot / 3, q = slot % 3;
                bool du = (r == 1);
                if (h == 0) dual0 = du; else dual1 = du;
                #pragma unroll
                for (int s = 0; s < 3; s++) {
                    int jj = 3 * q + s;
                    d[s] = (jj < 8) ? ((r ? A2 : A1) + 256 + c * 8 + jj) : scratch;
                }
            } else {
                d[0] = d[1] = d[2] = scratch;
            }
        }
    }

    // GEMV input pointers
    const float4* ev1 = nullptr;
    const float4* ev2 = nullptr;
    if (isZ) {
        const float* base = (role == 0) ? A1 : B2;
        ev1 = (const float4*)(base + w8 * 160 + g_l * 40);
        ev2 = (const float4*)(A2 + w8 * 160 + g_l * 40);   // used by role 0 only
    }

    __syncthreads();

    // ---- Step loop ----
    for (int t = 0; t <= NSTEP; t++) {
        // Window 1: z-GEMVs and out-GEMV, concurrent
        if (t < NSTEP && isZ && ((role == 0) || ((t & 1) == 0))) {
            float a0 = 0.0f, a1 = 0.0f;
            if (role == 0) {
                #pragma unroll
                for (int i = 0; i < 10; i++) {
                    float4 q = ev1[i];
                    float4 p = ev2[i];
                    q.x += p.x; q.y += p.y; q.z += p.z; q.w += p.w;
                    a0 += wreg[4*i+0] * q.x + wreg[4*i+1] * q.y;
                    a1 += wreg[4*i+2] * q.z + wreg[4*i+3] * q.w;
                }
            } else {
                #pragma unroll
                for (int i = 0; i < 10; i++) {
                    float4 q = ev1[i];
                    a0 += wreg[4*i+0] * q.x + wreg[4*i+1] * q.y;
                    a1 += wreg[4*i+2] * q.z + wreg[4*i+3] * q.w;
                }
            }
            float acc = a0 + a1;
            acc += __shfl_xor_sync(0xffffffffu, acc, 1);
            acc += __shfl_xor_sync(0xffffffffu, acc, 2);
            if (g_l == 0) redp[role * 64 + o_l * 8 + w8] = acc;
        }
        if (t >= 1 && !isZ) {
            const float4* wv = (const float4*)(wso + cw * 1024);
            const float4* zv = (const float4*)(A1 + 256);
            float acc = 0.0f;
            #pragma unroll
            for (int i = 0; i < 8; i++) {
                float4 wq = wv[lane + 32 * i];
                float4 zq = zv[lane + 32 * i];
                acc += wq.x * zq.x + wq.y * zq.y + wq.z * zq.z + wq.w * zq.w;
            }
            #pragma unroll
            for (int off = 16; off; off >>= 1)
                acc += __shfl_xor_sync(0xffffffffu, acc, off);
            if (lane == 0)
                out[(size_t)(t - 1) * 256 + o0 + cw] = tanhf(acc + bo);
        }
        __syncthreads();
        if (t == NSTEP) break;

        const unsigned tag = epoch * 512u + (unsigned)(t + 1);
        const float ftag = __uint_as_float(tag);
        float4* pubbuf = &g_pub[(t + 1) & 1][0];

        if (!isZ) {
            // Reduce + publish this CTA's 16 new state values (tagged chunks)
            const int r = cw;
            float v;
            if ((r == 0) || ((t & 1) == 0)) {
                float2 p = *(const float2*)(redp + r * 64 + o_l * 8 + 2 * g_l);
                v = p.x + p.y;
                v += __shfl_xor_sync(0xffffffffu, v, 1);
                v += __shfl_xor_sync(0xffffffffu, v, 2);
                v = tanhf(v + sbias[r * 8 + o_l]);
            } else {
                v = B2[256 + j0 + o_l];           // odd step: layer2 holds
            }
            if (g_l == 0) pubv[r * 8 + o_l] = v;
            __syncwarp();
            if (lane < 3) {
                int q = lane;
                float4 u;
                u.x = pubv[r * 8 + 3 * q];
                u.y = (3 * q + 1 < 8) ? pubv[r * 8 + 3 * q + 1] : 0.0f;
                u.z = (3 * q + 2 < 8) ? pubv[r * 8 + 3 * q + 2] : 0.0f;
                u.w = ftag;
                st_vol4(pubbuf + blockIdx.x * 6 + r * 3 + q, u);
            }
            // Stage x(t+1), prefetch x(t+2)
            int ct = tid - 512;
            if (t + 1 < NSTEP) {
                ((float4*)A1)[ct] = xreg4;
                ((float4*)B2)[ct] = xreg4;
                if (t + 2 < NSTEP)
                    xreg4 = ((const float4*)(x + ((size_t)(t + 2) * 2048 + 2047) * 256))[ct];
            }
        } else {
            // Poll tagged chunks for step t+1, scatter into SMEM state arrays
            const float4* p0 = pubbuf + tid;
            const float4* p1 = pubbuf + 512 + tid;
            bool got0 = false, got1 = (tid >= 256);
            float4 u0, u1;
            while (!(got0 && got1)) {
                if (!got0) { u0 = ld_vol4(p0); got0 = (__float_as_uint(u0.w) == tag); }
                if (!got1) { u1 = ld_vol4(p1); got1 = (__float_as_uint(u1.w) == tag); }
            }
            *d0[0] = u0.x; *d0[1] = u0.y; *d0[2] = u0.z;
            if (dual0) { d0[0][KEXT] = u0.x; d0[1][KEXT] = u0.y; d0[2][KEXT] = u0.z; }
            if (tid < 256) {
                *d1[0] = u1.x; *d1[1] = u1.y; *d1[2] = u1.z;
                if (dual1) { d1[0][KEXT] = u1.x; d1[1][KEXT] = u1.y; d1[2][KEXT] = u1.z; }
            }
        }
        __syncthreads();
    }
}

extern "C" void kernel_launch(void* const* d_in, const int* in_sizes, int n_in,
                              void* d_out, int out_size) {
    (void)in_sizes; (void)n_in; (void)out_size;
    const float* x      = (const float*)d_in[0];
    const float* W_in1  = (const float*)d_in[1];
    const float* b_in1  = (const float*)d_in[2];
    const float* W_rec1 = (const float*)d_in[3];
    const float* W_in2  = (const float*)d_in[4];
    const float* b_in2  = (const float*)d_in[5];
    const float* W_rec2 = (const float*)d_in[6];
    const float* W_out  = (const float*)d_in[7];
    const float* b_out  = (const float*)d_in[8];
    float* out = (float*)d_out;

    const size_t smem_bytes =
        (size_t)(2048 + 3 * KEXT + 128 + 16 + 16 + 4 + 8 * KEXT) * sizeof(float);

    cudaFuncSetAttribute(rnn_persistent_kernel,
                         cudaFuncAttributeMaxDynamicSharedMemorySize,
                         (int)smem_bytes);

    rnn_init_kernel<<<1, 1>>>();
    rnn_persistent_kernel<<<GRID, BLOCK, smem_bytes>>>(
        x, W_in1, b_in1, W_rec1, W_in2, b_in2, W_rec2, W_out, b_out, out);
}